// round 13
// baseline (speedup 1.0000x reference)
#include <cuda_runtime.h>
#include <cuda_fp16.h>
#include <cstdint>

// ---------------- problem dims ----------------
#define BSZ   2
#define QL    1024
#define HID   4096
#define NH    32
#define NKV   8
#define HD    128
#define NBLK  512
#define BLKSZ 16
#define SEQ   4096
#define MROWS (BSZ*QL)                 // 2048
#define QKVN  (NH*HD + 2*NKV*HD)       // 6144
#define WROWS (QKVN + HID)             // 10240
#define WOFF_O ((size_t)QKVN * HID)

// q pre-scale: (1/sqrt(128)) * log2(e)  -> softmax in exp2 domain
#define ASCALE ((float)(0.08838834764831845 * 1.4426950408889634))

// ---------------- device scratch ----------------
__device__ __half g_qkv[(size_t)MROWS * QKVN];   // fused QKV projection output (fp16)
__device__ __half g_xh [(size_t)MROWS * HID];    // activations fp16 (reused for attn out)
__device__ __half g_wf [(size_t)WROWS * HID];    // all weights fp16
__device__ __half g_qf [(size_t)BSZ * NH * QL * HD];   // Q fp16 (pre-scaled)
__device__ __half g_kf [(size_t)NBLK * NKV * BLKSZ * HD];  // K cache fp16
__device__ __half g_vf [(size_t)NBLK * NKV * BLKSZ * HD];  // V cache fp16

// ---------------- helpers ----------------
__device__ __forceinline__ uint32_t smem_u32(const void* p) {
    uint32_t a;
    asm("{ .reg .u64 t; cvta.to.shared.u64 t, %1; cvt.u32.u64 %0, t; }" : "=r"(a) : "l"(p));
    return a;
}
__device__ __forceinline__ void ldsm4(uint32_t* r, uint32_t addr) {
    asm volatile("ldmatrix.sync.aligned.m8n8.x4.shared.b16 {%0,%1,%2,%3}, [%4];"
                 : "=r"(r[0]), "=r"(r[1]), "=r"(r[2]), "=r"(r[3]) : "r"(addr));
}
__device__ __forceinline__ void ldsm4t(uint32_t* r, uint32_t addr) {
    asm volatile("ldmatrix.sync.aligned.m8n8.x4.trans.shared.b16 {%0,%1,%2,%3}, [%4];"
                 : "=r"(r[0]), "=r"(r[1]), "=r"(r[2]), "=r"(r[3]) : "r"(addr));
}
__device__ __forceinline__ void mma_f16(float* c, const uint32_t* a, uint32_t b0, uint32_t b1) {
    asm volatile("mma.sync.aligned.m16n8k16.row.col.f32.f16.f16.f32 "
                 "{%0,%1,%2,%3}, {%4,%5,%6,%7}, {%8,%9}, {%0,%1,%2,%3};"
                 : "+f"(c[0]), "+f"(c[1]), "+f"(c[2]), "+f"(c[3])
                 : "r"(a[0]), "r"(a[1]), "r"(a[2]), "r"(a[3]), "r"(b0), "r"(b1));
}
__device__ __forceinline__ float ex2f(float x) {
    float y; asm("ex2.approx.ftz.f32 %0, %1;" : "=f"(y) : "f"(x)); return y;
}
__device__ __forceinline__ uint32_t packh2(float a, float b) {
    __half2 t = __floats2half2_rn(a, b);
    return *(uint32_t*)&t;
}
__device__ __forceinline__ void cpasync16(uint32_t dst, const void* src) {
    asm volatile("cp.async.cg.shared.global [%0], [%1], 16;" :: "r"(dst), "l"(src));
}
#define CP_COMMIT() asm volatile("cp.async.commit_group;" ::: "memory")
#define CP_WAIT1()  asm volatile("cp.async.wait_group 1;" ::: "memory")
#define CP_WAIT0()  asm volatile("cp.async.wait_group 0;" ::: "memory")

// ---------------- fused preprocessing: 7 fp32->fp16 jobs in one launch ----------------
// n4 segment bases (units of 4 floats):
//  [0)        hidden -> xh          2,097,152
//  [2097152)  Wq     -> wf+0        4,194,304
//  [6291456)  Wk     -> wf+16777216 1,048,576
//  [7340032)  Wv     -> wf+20971520 1,048,576
//  [8388608)  Wo     -> wf+25165824 4,194,304
//  [12582912) kstore -> kf          2,097,152
//  [14680064) vstore -> vf          2,097,152
//  total 16,777,216 -> 65536 blocks of 256
__global__ __launch_bounds__(256) void prep_all(
    const float* __restrict__ hidden,
    const float* __restrict__ Wq, const float* __restrict__ Wk,
    const float* __restrict__ Wv, const float* __restrict__ Wo,
    const float* __restrict__ ks, const float* __restrict__ vs,
    __half* __restrict__ xh, __half* __restrict__ wf,
    __half* __restrict__ kf, __half* __restrict__ vf)
{
    int i = blockIdx.x * 256 + threadIdx.x;
    const float* src; __half* dst; int local;
    if      (i <  2097152) { src = hidden; dst = xh;                       local = i; }
    else if (i <  6291456) { src = Wq;     dst = wf;                       local = i - 2097152; }
    else if (i <  7340032) { src = Wk;     dst = wf + (size_t)16777216;    local = i - 6291456; }
    else if (i <  8388608) { src = Wv;     dst = wf + (size_t)20971520;    local = i - 7340032; }
    else if (i < 12582912) { src = Wo;     dst = wf + (size_t)25165824;    local = i - 8388608; }
    else if (i < 14680064) { src = ks;     dst = kf;                       local = i - 12582912; }
    else                   { src = vs;     dst = vf;                       local = i - 14680064; }
    float4 v = ((const float4*)src)[local];
    __half2* yp = (__half2*)(dst + (size_t)local * 4);
    yp[0] = __floats2half2_rn(v.x, v.y);
    yp[1] = __floats2half2_rn(v.z, v.w);
}

// ---------------- pipelined fp16 single-product GEMM (templated output) ----------------
#define TB2 8192                    // one 128x32 fp16 tile
#define BUF1 (2 * TB2)              // A, B

template <typename OutT>
__global__ __launch_bounds__(256) void gemm_f16_1p(
    const __half* __restrict__ Aa, const __half* __restrict__ Bw,
    OutT* __restrict__ C, int M, int N, int K)
{
    __shared__ __half smem[2][2][128 * 32];   // 32KB

    const int tid  = threadIdx.x;
    const int warp = tid >> 5, lane = tid & 31;
    const int wm = warp & 3, wn = warp >> 2;
    const int bm = blockIdx.y * 128, bn = blockIdx.x * 128;
    const uint32_t sb = smem_u32(smem);

    float acc[2][8][4];
#pragma unroll
    for (int i = 0; i < 2; i++)
#pragma unroll
        for (int j = 0; j < 8; j++)
#pragma unroll
            for (int e = 0; e < 4; e++) acc[i][j][e] = 0.f;

    const __half* g0 = Aa + (size_t)bm * K;
    const __half* g1 = Bw + (size_t)bn * K;

    int rowA = tid >> 2, kcA = tid & 3;
    int rowB = (tid + 256) >> 2, kcB = (tid + 256) & 3;
    uint32_t soffA = (uint32_t)(rowA * 32 + (((kcA + (rowA >> 1)) & 3) * 8)) * 2;
    uint32_t soffB = (uint32_t)(rowB * 32 + (((kcB + (rowB >> 1)) & 3) * 8)) * 2;

    const int nch = K / 32;

#define ISSUE_LOAD(buf, k0)                                                    \
    do {                                                                       \
        size_t gA = (size_t)rowA * K + (k0) + kcA * 8;                         \
        size_t gB = (size_t)rowB * K + (k0) + kcB * 8;                         \
        uint32_t base = sb + (buf) * BUF1;                                     \
        cpasync16(base + 0 * TB2 + soffA, g0 + gA);                            \
        cpasync16(base + 1 * TB2 + soffA, g1 + gA);                            \
        cpasync16(base + 0 * TB2 + soffB, g0 + gB);                            \
        cpasync16(base + 1 * TB2 + soffB, g1 + gB);                            \
        CP_COMMIT();                                                           \
    } while (0)

    ISSUE_LOAD(0, 0);

    for (int ch = 0; ch < nch; ch++) {
        const int buf = ch & 1;
        if (ch + 1 < nch) {
            ISSUE_LOAD(buf ^ 1, (ch + 1) * 32);
            CP_WAIT1();
        } else {
            CP_WAIT0();
        }
        __syncthreads();

        const uint32_t aBs = sb + buf * BUF1;
        const uint32_t bBs = aBs + TB2;

#pragma unroll
        for (int ks = 0; ks < 2; ks++) {
            uint32_t ah[2][4];
            {
                int r  = wm * 32 + (lane & 15);
                int cd = ks * 2 + (lane >> 4);
#pragma unroll
                for (int mt = 0; mt < 2; mt++) {
                    int row  = r + mt * 16;
                    int phys = (cd + (row >> 1)) & 3;
                    uint32_t off = (uint32_t)(row * 32 + phys * 8) * 2;
                    ldsm4(ah[mt], aBs + off);
                }
            }
#pragma unroll
            for (int nt4 = 0; nt4 < 4; nt4++) {
                int n    = wn * 64 + nt4 * 16 + (lane & 7) + ((lane >> 4) << 3);
                int cd   = ks * 2 + ((lane >> 3) & 1);
                int phys = (cd + (n >> 1)) & 3;
                uint32_t off = (uint32_t)(n * 32 + phys * 8) * 2;
                uint32_t bw[4];
                ldsm4(bw, bBs + off);
#pragma unroll
                for (int mt = 0; mt < 2; mt++) {
#pragma unroll
                    for (int p = 0; p < 2; p++) {
                        mma_f16(acc[mt][nt4 * 2 + p], ah[mt], bw[2 * p], bw[2 * p + 1]);
                    }
                }
            }
        }
        __syncthreads();
    }
#undef ISSUE_LOAD

#pragma unroll
    for (int mt = 0; mt < 2; mt++) {
#pragma unroll
        for (int nt = 0; nt < 8; nt++) {
            int row = bm + wm * 32 + mt * 16 + (lane >> 2);
            int col = bn + wn * 64 + nt * 8 + (lane & 3) * 2;
            float* cc = acc[mt][nt];
            if constexpr (sizeof(OutT) == 2) {
                *(uint32_t*)&C[(size_t)row * N + col]       = packh2(cc[0], cc[1]);
                *(uint32_t*)&C[(size_t)(row + 8) * N + col] = packh2(cc[2], cc[3]);
            } else {
                *(float2*)&C[(size_t)row * N + col]       = make_float2(cc[0], cc[1]);
                *(float2*)&C[(size_t)(row + 8) * N + col] = make_float2(cc[2], cc[3]);
            }
        }
    }
}

// ---------------- RoPE + fp16 round + cache scatter (fp16 qkv input) ----------------
__global__ __launch_bounds__(256) void rope_scatter_h(
    const __half* __restrict__ QKV,
    const float* __restrict__ cosp, const float* __restrict__ sinp,
    const int* __restrict__ ctx_ptrs,
    __half* __restrict__ qf,
    __half* __restrict__ kf, __half* __restrict__ vf)
{
    const int row = blockIdx.x;          // 0..2047
    const int b = row >> 10, t = row & 1023;
    const int tid = threadIdx.x;
    const float* crow = cosp + (size_t)t * HD;
    const float* srow = sinp + (size_t)t * HD;
    const __half* Qr = QKV + (size_t)row * QKVN;
    const __half* Kr = Qr + NH * HD;
    const __half* Vr = Kr + NKV * HD;

    // Q: rope, scale, fp16 round, store [b,h,t,d]
    for (int idx = tid; idx < NH * 64; idx += 256) {
        int h = idx >> 6, d = idx & 63;
        float x0 = __half2float(Qr[h * HD + d]);
        float x1 = __half2float(Qr[h * HD + d + 64]);
        float o0 = (x0 * crow[d]      - x1 * srow[d])      * ASCALE;
        float o1 = (x1 * crow[d + 64] + x0 * srow[d + 64]) * ASCALE;
        size_t base = ((size_t)(b * NH + h) * QL + t) * HD;
        qf[base + d]      = __float2half_rn(o0);
        qf[base + d + 64] = __float2half_rn(o1);
    }

    const int blk  = ctx_ptrs[b * (QL / BLKSZ) + (t >> 4)];
    const int rrow = t & 15;

    // K: rope, fp16 round, scatter
    for (int idx = tid; idx < NKV * 64; idx += 256) {
        int h = idx >> 6, d = idx & 63;
        float x0 = __half2float(Kr[h * HD + d]);
        float x1 = __half2float(Kr[h * HD + d + 64]);
        float o0 = x0 * crow[d]      - x1 * srow[d];
        float o1 = x1 * crow[d + 64] + x0 * srow[d + 64];
        size_t base = (((size_t)blk * NKV + h) * BLKSZ + rrow) * HD;
        kf[base + d]      = __float2half_rn(o0);
        kf[base + d + 64] = __float2half_rn(o1);
    }

    // V: scatter (already fp16)
    for (int idx = tid; idx < NKV * HD; idx += 256) {
        int h = idx >> 7, d = idx & 127;
        vf[(((size_t)blk * NKV + h) * BLKSZ + rrow) * HD + d] = Vr[h * HD + d];
    }
}

// ---------------- flash attention: single-product fp16, q-tile 128, 8 warps ----------------
// smem: Q 128x128 (32KB) + KV 64x128 (16KB) = 48KB.
#define ATT_SMEM2 ((128 * 128 + 64 * 128) * 2)

__global__ __launch_bounds__(256, 2) void attn_mma(
    const __half* __restrict__ gqf,
    const __half* __restrict__ gkf, const __half* __restrict__ gvf,
    const int* __restrict__ kvlut, const int* __restrict__ prefix_ptr,
    __half* __restrict__ oh)
{
    extern __shared__ __align__(16) char dynsm[];
    __half* sQ  = (__half*)dynsm;        // 128 x 128
    __half* sKV = sQ + 128 * 128;        // 64 x 128 (K, then V)
    const uint32_t bQ = smem_u32(sQ), bKV = smem_u32(sKV);

    const int qtile = blockIdx.x, h = blockIdx.y, b = blockIdx.z;
    const int kvh = h >> 2;
    const int prefix = prefix_ptr ? *prefix_ptr : 3072;
    const int tid = threadIdx.x;
    const int warp = tid >> 5, lane = tid & 31;
    const int qr = warp * 16;            // 0..112
    const int q0 = qtile * 128;
    const int* lut = kvlut + b * (SEQ / BLKSZ);

    // load Q tile (128 rows)
    {
        const __half* src = gqf + ((size_t)(b * NH + h) * QL + q0) * HD;
        for (int i = tid; i < 128 * 16; i += 256) {
            int row = i >> 4, c = i & 15;
            int phys = (c ^ (row & 7)) << 3;
            *(uint4*)&sQ[row * 128 + phys] = *(const uint4*)(src + (size_t)row * HD + c * 8);
        }
    }

    float O[16][4];
#pragma unroll
    for (int i = 0; i < 16; i++)
#pragma unroll
        for (int e = 0; e < 4; e++) O[i][e] = 0.f;
    float m0 = -1e30f, m1 = -1e30f, l0 = 0.f, l1 = 0.f;

    const int plim = prefix + q0;        // lowest q row's absolute position
    const int kv_end = plim + 128;
    const int qa0 = plim + qr + (lane >> 2);
    const int qa1 = qa0 + 8;

    for (int s0 = 0; s0 < kv_end; s0 += 64) {
        __syncthreads();
        for (int i = tid; i < 64 * 16; i += 256) {
            int row = i >> 4, c = i & 15;
            int s = s0 + row;
            int blk = lut[s >> 4];
            size_t base = (((size_t)blk * NKV + kvh) * BLKSZ + (s & 15)) * HD + c * 8;
            int phys = (c ^ (row & 7)) << 3;
            *(uint4*)&sKV[row * 128 + phys] = *(const uint4*)(gkf + base);
        }
        __syncthreads();

        // ---- S = Q K^T (single product) ----
        float S[8][4];
#pragma unroll
        for (int i = 0; i < 8; i++)
#pragma unroll
            for (int e = 0; e < 4; e++) S[i][e] = 0.f;

#pragma unroll
        for (int ks = 0; ks < 8; ks++) {
            uint32_t aq[4];
            {
                int arow = qr + (lane & 15);
                int ac = ks * 2 + (lane >> 4);
                uint32_t aoff = (uint32_t)(arow * 128 + ((ac ^ (arow & 7)) << 3)) * 2;
                ldsm4(aq, bQ + aoff);
            }
            int brow_b = (lane & 7) + ((lane >> 4) << 3);
            int bc = ks * 2 + ((lane >> 3) & 1);
#pragma unroll
            for (int ng = 0; ng < 4; ng++) {
                int brow = ng * 16 + brow_b;
                uint32_t boff = (uint32_t)(brow * 128 + ((bc ^ (brow & 7)) << 3)) * 2;
                uint32_t kw[4];
                ldsm4(kw, bKV + boff);
                mma_f16(S[2 * ng],     aq, kw[0], kw[1]);
                mma_f16(S[2 * ng + 1], aq, kw[2], kw[3]);
            }
        }

        if (s0 + 63 > plim) {
#pragma unroll
            for (int nt = 0; nt < 8; nt++) {
                int colb = s0 + nt * 8 + ((lane & 3) << 1);
                if (colb     > qa0) S[nt][0] = -1e30f;
                if (colb + 1 > qa0) S[nt][1] = -1e30f;
                if (colb     > qa1) S[nt][2] = -1e30f;
                if (colb + 1 > qa1) S[nt][3] = -1e30f;
            }
        }

        float mx0 = -1e30f, mx1 = -1e30f;
#pragma unroll
        for (int nt = 0; nt < 8; nt++) {
            mx0 = fmaxf(mx0, fmaxf(S[nt][0], S[nt][1]));
            mx1 = fmaxf(mx1, fmaxf(S[nt][2], S[nt][3]));
        }
        mx0 = fmaxf(mx0, __shfl_xor_sync(0xffffffffu, mx0, 1));
        mx0 = fmaxf(mx0, __shfl_xor_sync(0xffffffffu, mx0, 2));
        mx1 = fmaxf(mx1, __shfl_xor_sync(0xffffffffu, mx1, 1));
        mx1 = fmaxf(mx1, __shfl_xor_sync(0xffffffffu, mx1, 2));
        float mn0 = fmaxf(m0, mx0), mn1 = fmaxf(m1, mx1);
        float f0 = ex2f(m0 - mn0), f1 = ex2f(m1 - mn1);
        m0 = mn0; m1 = mn1;

        float rs0 = 0.f, rs1 = 0.f;
#pragma unroll
        for (int nt = 0; nt < 8; nt++) {
            S[nt][0] = ex2f(S[nt][0] - mn0); rs0 += S[nt][0];
            S[nt][1] = ex2f(S[nt][1] - mn0); rs0 += S[nt][1];
            S[nt][2] = ex2f(S[nt][2] - mn1); rs1 += S[nt][2];
            S[nt][3] = ex2f(S[nt][3] - mn1); rs1 += S[nt][3];
        }
        rs0 += __shfl_xor_sync(0xffffffffu, rs0, 1);
        rs0 += __shfl_xor_sync(0xffffffffu, rs0, 2);
        rs1 += __shfl_xor_sync(0xffffffffu, rs1, 1);
        rs1 += __shfl_xor_sync(0xffffffffu, rs1, 2);
        l0 = l0 * f0 + rs0;
        l1 = l1 * f1 + rs1;

#pragma unroll
        for (int nt = 0; nt < 16; nt++) {
            O[nt][0] *= f0; O[nt][1] *= f0; O[nt][2] *= f1; O[nt][3] *= f1;
        }

        // ---- pack P (single fp16) ----
        uint32_t PH[4][4];
#pragma unroll
        for (int kt = 0; kt < 4; kt++) {
            int e = 2 * kt, o = 2 * kt + 1;
            PH[kt][0] = packh2(S[e][0], S[e][1]);
            PH[kt][1] = packh2(S[e][2], S[e][3]);
            PH[kt][2] = packh2(S[o][0], S[o][1]);
            PH[kt][3] = packh2(S[o][2], S[o][3]);
        }

        __syncthreads();
        for (int i = tid; i < 64 * 16; i += 256) {
            int row = i >> 4, c = i & 15;
            int s = s0 + row;
            int blk = lut[s >> 4];
            size_t base = (((size_t)blk * NKV + kvh) * BLKSZ + (s & 15)) * HD + c * 8;
            int phys = (c ^ (row & 7)) << 3;
            *(uint4*)&sKV[row * 128 + phys] = *(const uint4*)(gvf + base);
        }
        __syncthreads();

        // ---- O += P V (single product) ----
#pragma unroll
        for (int kt = 0; kt < 4; kt++) {
            int vrow = kt * 16 + (((lane >> 3) & 1) << 3) + (lane & 7);
            int vc0 = lane >> 4;
#pragma unroll
            for (int vg = 0; vg < 8; vg++) {
                int c = vg * 2 + vc0;
                uint32_t off = (uint32_t)(vrow * 128 + ((c ^ (vrow & 7)) << 3)) * 2;
                uint32_t vw[4];
                ldsm4t(vw, bKV + off);
                mma_f16(O[2 * vg],     PH[kt], vw[0], vw[1]);
                mma_f16(O[2 * vg + 1], PH[kt], vw[2], vw[3]);
            }
        }
    }

    // epilogue: normalize, round to fp16, write [b,t,h*128+d]
    float inv0 = 1.f / l0, inv1 = 1.f / l1;
    int r0 = q0 + qr + (lane >> 2);
    int r1 = r0 + 8;
#pragma unroll
    for (int nt = 0; nt < 16; nt++) {
        int d = h * HD + nt * 8 + ((lane & 3) << 1);
        *(uint32_t*)(oh + (size_t)(b * QL + r0) * HID + d) =
            packh2(O[nt][0] * inv0, O[nt][1] * inv0);
        *(uint32_t*)(oh + (size_t)(b * QL + r1) * HID + d) =
            packh2(O[nt][2] * inv1, O[nt][3] * inv1);
    }
}

// ---------------- launcher ----------------
extern "C" void kernel_launch(void* const* d_in, const int* in_sizes, int n_in,
                              void* d_out, int out_size)
{
    const float* hidden = (const float*)d_in[0];
    const float* Wq     = (const float*)d_in[1];
    const float* Wk     = (const float*)d_in[2];
    const float* Wv     = (const float*)d_in[3];
    const float* Wo     = (const float*)d_in[4];
    const float* cosp   = (const float*)d_in[5];
    const float* sinp   = (const float*)d_in[6];
    const float* kstore = (const float*)d_in[7];
    const float* vstore = (const float*)d_in[8];
    const int*   kvlut  = (const int*)d_in[9];
    const int*   ctxptr = (const int*)d_in[10];
    const int*   prefix = (n_in >= 12) ? (const int*)d_in[11] : nullptr;
    float* out = (float*)d_out;

    __half *qkv, *xh, *wf, *qf, *kf, *vf;
    cudaGetSymbolAddress((void**)&qkv, g_qkv);
    cudaGetSymbolAddress((void**)&xh,  g_xh);
    cudaGetSymbolAddress((void**)&wf,  g_wf);
    cudaGetSymbolAddress((void**)&qf,  g_qf);
    cudaGetSymbolAddress((void**)&kf,  g_kf);
    cudaGetSymbolAddress((void**)&vf,  g_vf);

    cudaFuncSetAttribute(attn_mma, cudaFuncAttributeMaxDynamicSharedMemorySize, ATT_SMEM2);

    // all fp32->fp16 preprocessing in one launch
    prep_all<<<65536, 256>>>(hidden, Wq, Wk, Wv, Wo, kstore, vstore, xh, wf, kf, vf);

    // fused QKV projection (fp16 output)
    gemm_f16_1p<__half><<<dim3(QKVN / 128, MROWS / 128), 256>>>(
        xh, wf, qkv, MROWS, QKVN, HID);

    // RoPE + round + scatter
    rope_scatter_h<<<MROWS, 256>>>(qkv, cosp, sinp, ctxptr, qf, kf, vf);

    // attention (q-tile 128; writes fp16 output into xh)
    attn_mma<<<dim3(QL / 128, NH, BSZ), 256, ATT_SMEM2>>>(
        qf, kf, vf, kvlut, prefix, xh);

    // O projection (fp32 output to d_out)
    gemm_f16_1p<float><<<dim3(HID / 128, MROWS / 128), 256>>>(
        xh, wf + WOFF_O, out, MROWS, HID, HID);
}

// round 14
// speedup vs baseline: 1.2060x; 1.2060x over previous
#include <cuda_runtime.h>
#include <cuda_fp16.h>
#include <cstdint>

// ---------------- problem dims ----------------
#define BSZ   2
#define QL    1024
#define HID   4096
#define NH    32
#define NKV   8
#define HD    128
#define NBLK  512
#define BLKSZ 16
#define SEQ   4096
#define MROWS (BSZ*QL)                 // 2048
#define QKVN  (NH*HD + 2*NKV*HD)       // 6144
#define WROWS (QKVN + HID)             // 10240
#define WOFF_O ((size_t)QKVN * HID)

// q pre-scale: (1/sqrt(128)) * log2(e)  -> softmax in exp2 domain
#define ASCALE ((float)(0.08838834764831845 * 1.4426950408889634))

// ---------------- device scratch ----------------
__device__ __half g_qkv[(size_t)MROWS * QKVN];   // fused QKV projection output (fp16)
__device__ __half g_xh [(size_t)MROWS * HID];    // activations fp16 (reused for attn out)
__device__ __half g_wf [(size_t)WROWS * HID];    // all weights fp16
__device__ __half g_qf [(size_t)BSZ * NH * QL * HD];   // Q fp16 (pre-scaled)
__device__ __half g_kf [(size_t)NBLK * NKV * BLKSZ * HD];  // K cache fp16
__device__ __half g_vf [(size_t)NBLK * NKV * BLKSZ * HD];  // V cache fp16

// ---------------- helpers ----------------
__device__ __forceinline__ uint32_t smem_u32(const void* p) {
    uint32_t a;
    asm("{ .reg .u64 t; cvta.to.shared.u64 t, %1; cvt.u32.u64 %0, t; }" : "=r"(a) : "l"(p));
    return a;
}
__device__ __forceinline__ void ldsm4(uint32_t* r, uint32_t addr) {
    asm volatile("ldmatrix.sync.aligned.m8n8.x4.shared.b16 {%0,%1,%2,%3}, [%4];"
                 : "=r"(r[0]), "=r"(r[1]), "=r"(r[2]), "=r"(r[3]) : "r"(addr));
}
__device__ __forceinline__ void ldsm4t(uint32_t* r, uint32_t addr) {
    asm volatile("ldmatrix.sync.aligned.m8n8.x4.trans.shared.b16 {%0,%1,%2,%3}, [%4];"
                 : "=r"(r[0]), "=r"(r[1]), "=r"(r[2]), "=r"(r[3]) : "r"(addr));
}
__device__ __forceinline__ void mma_f16(float* c, const uint32_t* a, uint32_t b0, uint32_t b1) {
    asm volatile("mma.sync.aligned.m16n8k16.row.col.f32.f16.f16.f32 "
                 "{%0,%1,%2,%3}, {%4,%5,%6,%7}, {%8,%9}, {%0,%1,%2,%3};"
                 : "+f"(c[0]), "+f"(c[1]), "+f"(c[2]), "+f"(c[3])
                 : "r"(a[0]), "r"(a[1]), "r"(a[2]), "r"(a[3]), "r"(b0), "r"(b1));
}
__device__ __forceinline__ float ex2f(float x) {
    float y; asm("ex2.approx.ftz.f32 %0, %1;" : "=f"(y) : "f"(x)); return y;
}
__device__ __forceinline__ uint32_t packh2(float a, float b) {
    __half2 t = __floats2half2_rn(a, b);
    return *(uint32_t*)&t;
}
__device__ __forceinline__ void cpasync16(uint32_t dst, const void* src) {
    asm volatile("cp.async.cg.shared.global [%0], [%1], 16;" :: "r"(dst), "l"(src));
}
#define CP_COMMIT() asm volatile("cp.async.commit_group;" ::: "memory")
#define CP_WAIT1()  asm volatile("cp.async.wait_group 1;" ::: "memory")
#define CP_WAIT0()  asm volatile("cp.async.wait_group 0;" ::: "memory")

// ---------------- fused preprocessing: 7 fp32->fp16 jobs in one launch ----------------
__global__ __launch_bounds__(256) void prep_all(
    const float* __restrict__ hidden,
    const float* __restrict__ Wq, const float* __restrict__ Wk,
    const float* __restrict__ Wv, const float* __restrict__ Wo,
    const float* __restrict__ ks, const float* __restrict__ vs,
    __half* __restrict__ xh, __half* __restrict__ wf,
    __half* __restrict__ kf, __half* __restrict__ vf)
{
    int i = blockIdx.x * 256 + threadIdx.x;
    const float* src; __half* dst; int local;
    if      (i <  2097152) { src = hidden; dst = xh;                       local = i; }
    else if (i <  6291456) { src = Wq;     dst = wf;                       local = i - 2097152; }
    else if (i <  7340032) { src = Wk;     dst = wf + (size_t)16777216;    local = i - 6291456; }
    else if (i <  8388608) { src = Wv;     dst = wf + (size_t)20971520;    local = i - 7340032; }
    else if (i < 12582912) { src = Wo;     dst = wf + (size_t)25165824;    local = i - 8388608; }
    else if (i < 14680064) { src = ks;     dst = kf;                       local = i - 12582912; }
    else                   { src = vs;     dst = vf;                       local = i - 14680064; }
    float4 v = ((const float4*)src)[local];
    __half2* yp = (__half2*)(dst + (size_t)local * 4);
    yp[0] = __floats2half2_rn(v.x, v.y);
    yp[1] = __floats2half2_rn(v.z, v.w);
}

// ---------------- pipelined fp16 single-product GEMM (templated output) ----------------
#define TB2 8192                    // one 128x32 fp16 tile
#define BUF1 (2 * TB2)              // A, B

template <typename OutT>
__global__ __launch_bounds__(256) void gemm_f16_1p(
    const __half* __restrict__ Aa, const __half* __restrict__ Bw,
    OutT* __restrict__ C, int M, int N, int K)
{
    __shared__ __half smem[2][2][128 * 32];   // 32KB

    const int tid  = threadIdx.x;
    const int warp = tid >> 5, lane = tid & 31;
    const int wm = warp & 3, wn = warp >> 2;
    const int bm = blockIdx.y * 128, bn = blockIdx.x * 128;
    const uint32_t sb = smem_u32(smem);

    float acc[2][8][4];
#pragma unroll
    for (int i = 0; i < 2; i++)
#pragma unroll
        for (int j = 0; j < 8; j++)
#pragma unroll
            for (int e = 0; e < 4; e++) acc[i][j][e] = 0.f;

    const __half* g0 = Aa + (size_t)bm * K;
    const __half* g1 = Bw + (size_t)bn * K;

    int rowA = tid >> 2, kcA = tid & 3;
    int rowB = (tid + 256) >> 2, kcB = (tid + 256) & 3;
    uint32_t soffA = (uint32_t)(rowA * 32 + (((kcA + (rowA >> 1)) & 3) * 8)) * 2;
    uint32_t soffB = (uint32_t)(rowB * 32 + (((kcB + (rowB >> 1)) & 3) * 8)) * 2;

    const int nch = K / 32;

#define ISSUE_LOAD(buf, k0)                                                    \
    do {                                                                       \
        size_t gA = (size_t)rowA * K + (k0) + kcA * 8;                         \
        size_t gB = (size_t)rowB * K + (k0) + kcB * 8;                         \
        uint32_t base = sb + (buf) * BUF1;                                     \
        cpasync16(base + 0 * TB2 + soffA, g0 + gA);                            \
        cpasync16(base + 1 * TB2 + soffA, g1 + gA);                            \
        cpasync16(base + 0 * TB2 + soffB, g0 + gB);                            \
        cpasync16(base + 1 * TB2 + soffB, g1 + gB);                            \
        CP_COMMIT();                                                           \
    } while (0)

    ISSUE_LOAD(0, 0);

    for (int ch = 0; ch < nch; ch++) {
        const int buf = ch & 1;
        if (ch + 1 < nch) {
            ISSUE_LOAD(buf ^ 1, (ch + 1) * 32);
            CP_WAIT1();
        } else {
            CP_WAIT0();
        }
        __syncthreads();

        const uint32_t aBs = sb + buf * BUF1;
        const uint32_t bBs = aBs + TB2;

#pragma unroll
        for (int ks = 0; ks < 2; ks++) {
            uint32_t ah[2][4];
            {
                int r  = wm * 32 + (lane & 15);
                int cd = ks * 2 + (lane >> 4);
#pragma unroll
                for (int mt = 0; mt < 2; mt++) {
                    int row  = r + mt * 16;
                    int phys = (cd + (row >> 1)) & 3;
                    uint32_t off = (uint32_t)(row * 32 + phys * 8) * 2;
                    ldsm4(ah[mt], aBs + off);
                }
            }
#pragma unroll
            for (int nt4 = 0; nt4 < 4; nt4++) {
                int n    = wn * 64 + nt4 * 16 + (lane & 7) + ((lane >> 4) << 3);
                int cd   = ks * 2 + ((lane >> 3) & 1);
                int phys = (cd + (n >> 1)) & 3;
                uint32_t off = (uint32_t)(n * 32 + phys * 8) * 2;
                uint32_t bw[4];
                ldsm4(bw, bBs + off);
#pragma unroll
                for (int mt = 0; mt < 2; mt++) {
#pragma unroll
                    for (int p = 0; p < 2; p++) {
                        mma_f16(acc[mt][nt4 * 2 + p], ah[mt], bw[2 * p], bw[2 * p + 1]);
                    }
                }
            }
        }
        __syncthreads();
    }
#undef ISSUE_LOAD

#pragma unroll
    for (int mt = 0; mt < 2; mt++) {
#pragma unroll
        for (int nt = 0; nt < 8; nt++) {
            int row = bm + wm * 32 + mt * 16 + (lane >> 2);
            int col = bn + wn * 64 + nt * 8 + (lane & 3) * 2;
            float* cc = acc[mt][nt];
            if constexpr (sizeof(OutT) == 2) {
                *(uint32_t*)&C[(size_t)row * N + col]       = packh2(cc[0], cc[1]);
                *(uint32_t*)&C[(size_t)(row + 8) * N + col] = packh2(cc[2], cc[3]);
            } else {
                *(float2*)&C[(size_t)row * N + col]       = make_float2(cc[0], cc[1]);
                *(float2*)&C[(size_t)(row + 8) * N + col] = make_float2(cc[2], cc[3]);
            }
        }
    }
}

// ---------------- RoPE + fp16 round + cache scatter (fp16 qkv input) ----------------
__global__ __launch_bounds__(256) void rope_scatter_h(
    const __half* __restrict__ QKV,
    const float* __restrict__ cosp, const float* __restrict__ sinp,
    const int* __restrict__ ctx_ptrs,
    __half* __restrict__ qf,
    __half* __restrict__ kf, __half* __restrict__ vf)
{
    const int row = blockIdx.x;          // 0..2047
    const int b = row >> 10, t = row & 1023;
    const int tid = threadIdx.x;
    const float* crow = cosp + (size_t)t * HD;
    const float* srow = sinp + (size_t)t * HD;
    const __half* Qr = QKV + (size_t)row * QKVN;
    const __half* Kr = Qr + NH * HD;
    const __half* Vr = Kr + NKV * HD;

    for (int idx = tid; idx < NH * 64; idx += 256) {
        int h = idx >> 6, d = idx & 63;
        float x0 = __half2float(Qr[h * HD + d]);
        float x1 = __half2float(Qr[h * HD + d + 64]);
        float o0 = (x0 * crow[d]      - x1 * srow[d])      * ASCALE;
        float o1 = (x1 * crow[d + 64] + x0 * srow[d + 64]) * ASCALE;
        size_t base = ((size_t)(b * NH + h) * QL + t) * HD;
        qf[base + d]      = __float2half_rn(o0);
        qf[base + d + 64] = __float2half_rn(o1);
    }

    const int blk  = ctx_ptrs[b * (QL / BLKSZ) + (t >> 4)];
    const int rrow = t & 15;

    for (int idx = tid; idx < NKV * 64; idx += 256) {
        int h = idx >> 6, d = idx & 63;
        float x0 = __half2float(Kr[h * HD + d]);
        float x1 = __half2float(Kr[h * HD + d + 64]);
        float o0 = x0 * crow[d]      - x1 * srow[d];
        float o1 = x1 * crow[d + 64] + x0 * srow[d + 64];
        size_t base = (((size_t)blk * NKV + h) * BLKSZ + rrow) * HD;
        kf[base + d]      = __float2half_rn(o0);
        kf[base + d + 64] = __float2half_rn(o1);
    }

    for (int idx = tid; idx < NKV * HD; idx += 256) {
        int h = idx >> 7, d = idx & 127;
        vf[(((size_t)blk * NKV + h) * BLKSZ + rrow) * HD + d] = Vr[h * HD + d];
    }
}

// ---------------- flash attention: single-product fp16, q-tile 64, 4 warps ----------------
// smem: Q + KV = 32KB. cp.async fills. Target 4 CTAs/SM.
#define ATT_SMEM2 (2 * 64 * 128 * 2)

__global__ __launch_bounds__(128, 4) void attn_mma(
    const __half* __restrict__ gqf,
    const __half* __restrict__ gkf, const __half* __restrict__ gvf,
    const int* __restrict__ kvlut, const int* __restrict__ prefix_ptr,
    __half* __restrict__ oh)
{
    extern __shared__ __align__(16) char dynsm[];
    __half* sQ  = (__half*)dynsm;
    __half* sKV = sQ + 64 * 128;    // K, then reused for V
    const uint32_t bQ = smem_u32(sQ), bKV = smem_u32(sKV);

    const int qtile = blockIdx.x, h = blockIdx.y, b = blockIdx.z;
    const int kvh = h >> 2;
    const int prefix = prefix_ptr ? *prefix_ptr : 3072;
    const int tid = threadIdx.x;
    const int warp = tid >> 5, lane = tid & 31;
    const int qr = warp * 16;
    const int q0 = qtile * 64;
    const int* lut = kvlut + b * (SEQ / BLKSZ);

    // load Q tile via cp.async
    {
        const __half* src = gqf + ((size_t)(b * NH + h) * QL + q0) * HD;
        for (int i = tid; i < 64 * 16; i += 128) {
            int row = i >> 4, c = i & 15;
            int phys = (c ^ (row & 7)) << 3;
            cpasync16(bQ + (uint32_t)(row * 128 + phys) * 2,
                      src + (size_t)row * HD + c * 8);
        }
        CP_COMMIT();
    }

    float O[16][4];
#pragma unroll
    for (int i = 0; i < 16; i++)
#pragma unroll
        for (int e = 0; e < 4; e++) O[i][e] = 0.f;
    float m0 = -1e30f, m1 = -1e30f, l0 = 0.f, l1 = 0.f;

    const int plim = prefix + q0;
    const int kv_end = plim + 64;
    const int qa0 = plim + qr + (lane >> 2);
    const int qa1 = qa0 + 8;

    for (int s0 = 0; s0 < kv_end; s0 += 64) {
        __syncthreads();   // prior V readers done before overwrite
        // K fill via cp.async (gather through LUT)
        for (int i = tid; i < 64 * 16; i += 128) {
            int row = i >> 4, c = i & 15;
            int s = s0 + row;
            int blk = lut[s >> 4];
            size_t base = (((size_t)blk * NKV + kvh) * BLKSZ + (s & 15)) * HD + c * 8;
            int phys = (c ^ (row & 7)) << 3;
            cpasync16(bKV + (uint32_t)(row * 128 + phys) * 2, gkf + base);
        }
        CP_COMMIT();
        CP_WAIT0();
        __syncthreads();

        // ---- S = Q K^T (single product) ----
        float S[8][4];
#pragma unroll
        for (int i = 0; i < 8; i++)
#pragma unroll
            for (int e = 0; e < 4; e++) S[i][e] = 0.f;

#pragma unroll
        for (int ks = 0; ks < 8; ks++) {
            uint32_t aq[4];
            {
                int arow = qr + (lane & 15);
                int ac = ks * 2 + (lane >> 4);
                uint32_t aoff = (uint32_t)(arow * 128 + ((ac ^ (arow & 7)) << 3)) * 2;
                ldsm4(aq, bQ + aoff);
            }
            int brow_b = (lane & 7) + ((lane >> 4) << 3);
            int bc = ks * 2 + ((lane >> 3) & 1);
#pragma unroll
            for (int ng = 0; ng < 4; ng++) {
                int brow = ng * 16 + brow_b;
                uint32_t boff = (uint32_t)(brow * 128 + ((bc ^ (brow & 7)) << 3)) * 2;
                uint32_t kw[4];
                ldsm4(kw, bKV + boff);
                mma_f16(S[2 * ng],     aq, kw[0], kw[1]);
                mma_f16(S[2 * ng + 1], aq, kw[2], kw[3]);
            }
        }

        if (s0 + 63 > plim) {
#pragma unroll
            for (int nt = 0; nt < 8; nt++) {
                int colb = s0 + nt * 8 + ((lane & 3) << 1);
                if (colb     > qa0) S[nt][0] = -1e30f;
                if (colb + 1 > qa0) S[nt][1] = -1e30f;
                if (colb     > qa1) S[nt][2] = -1e30f;
                if (colb + 1 > qa1) S[nt][3] = -1e30f;
            }
        }

        float mx0 = -1e30f, mx1 = -1e30f;
#pragma unroll
        for (int nt = 0; nt < 8; nt++) {
            mx0 = fmaxf(mx0, fmaxf(S[nt][0], S[nt][1]));
            mx1 = fmaxf(mx1, fmaxf(S[nt][2], S[nt][3]));
        }
        mx0 = fmaxf(mx0, __shfl_xor_sync(0xffffffffu, mx0, 1));
        mx0 = fmaxf(mx0, __shfl_xor_sync(0xffffffffu, mx0, 2));
        mx1 = fmaxf(mx1, __shfl_xor_sync(0xffffffffu, mx1, 1));
        mx1 = fmaxf(mx1, __shfl_xor_sync(0xffffffffu, mx1, 2));
        float mn0 = fmaxf(m0, mx0), mn1 = fmaxf(m1, mx1);
        float f0 = ex2f(m0 - mn0), f1 = ex2f(m1 - mn1);
        m0 = mn0; m1 = mn1;

        float rs0 = 0.f, rs1 = 0.f;
#pragma unroll
        for (int nt = 0; nt < 8; nt++) {
            S[nt][0] = ex2f(S[nt][0] - mn0); rs0 += S[nt][0];
            S[nt][1] = ex2f(S[nt][1] - mn0); rs0 += S[nt][1];
            S[nt][2] = ex2f(S[nt][2] - mn1); rs1 += S[nt][2];
            S[nt][3] = ex2f(S[nt][3] - mn1); rs1 += S[nt][3];
        }
        rs0 += __shfl_xor_sync(0xffffffffu, rs0, 1);
        rs0 += __shfl_xor_sync(0xffffffffu, rs0, 2);
        rs1 += __shfl_xor_sync(0xffffffffu, rs1, 1);
        rs1 += __shfl_xor_sync(0xffffffffu, rs1, 2);
        l0 = l0 * f0 + rs0;
        l1 = l1 * f1 + rs1;

#pragma unroll
        for (int nt = 0; nt < 16; nt++) {
            O[nt][0] *= f0; O[nt][1] *= f0; O[nt][2] *= f1; O[nt][3] *= f1;
        }

        // ---- pack P (single fp16) ----
        uint32_t PH[4][4];
#pragma unroll
        for (int kt = 0; kt < 4; kt++) {
            int e = 2 * kt, o = 2 * kt + 1;
            PH[kt][0] = packh2(S[e][0], S[e][1]);
            PH[kt][1] = packh2(S[e][2], S[e][3]);
            PH[kt][2] = packh2(S[o][0], S[o][1]);
            PH[kt][3] = packh2(S[o][2], S[o][3]);
        }

        __syncthreads();   // all warps done reading K smem
        // V fill via cp.async
        for (int i = tid; i < 64 * 16; i += 128) {
            int row = i >> 4, c = i & 15;
            int s = s0 + row;
            int blk = lut[s >> 4];
            size_t base = (((size_t)blk * NKV + kvh) * BLKSZ + (s & 15)) * HD + c * 8;
            int phys = (c ^ (row & 7)) << 3;
            cpasync16(bKV + (uint32_t)(row * 128 + phys) * 2, gvf + base);
        }
        CP_COMMIT();
        CP_WAIT0();
        __syncthreads();

        // ---- O += P V (single product) ----
#pragma unroll
        for (int kt = 0; kt < 4; kt++) {
            int vrow = kt * 16 + (((lane >> 3) & 1) << 3) + (lane & 7);
            int vc0 = lane >> 4;
#pragma unroll
            for (int vg = 0; vg < 8; vg++) {
                int c = vg * 2 + vc0;
                uint32_t off = (uint32_t)(vrow * 128 + ((c ^ (vrow & 7)) << 3)) * 2;
                uint32_t vw[4];
                ldsm4t(vw, bKV + off);
                mma_f16(O[2 * vg],     PH[kt], vw[0], vw[1]);
                mma_f16(O[2 * vg + 1], PH[kt], vw[2], vw[3]);
            }
        }
    }

    // epilogue: normalize, round to fp16, write [b,t,h*128+d]
    float inv0 = 1.f / l0, inv1 = 1.f / l1;
    int r0 = q0 + qr + (lane >> 2);
    int r1 = r0 + 8;
#pragma unroll
    for (int nt = 0; nt < 16; nt++) {
        int d = h * HD + nt * 8 + ((lane & 3) << 1);
        *(uint32_t*)(oh + (size_t)(b * QL + r0) * HID + d) =
            packh2(O[nt][0] * inv0, O[nt][1] * inv0);
        *(uint32_t*)(oh + (size_t)(b * QL + r1) * HID + d) =
            packh2(O[nt][2] * inv1, O[nt][3] * inv1);
    }
}

// ---------------- launcher ----------------
extern "C" void kernel_launch(void* const* d_in, const int* in_sizes, int n_in,
                              void* d_out, int out_size)
{
    const float* hidden = (const float*)d_in[0];
    const float* Wq     = (const float*)d_in[1];
    const float* Wk     = (const float*)d_in[2];
    const float* Wv     = (const float*)d_in[3];
    const float* Wo     = (const float*)d_in[4];
    const float* cosp   = (const float*)d_in[5];
    const float* sinp   = (const float*)d_in[6];
    const float* kstore = (const float*)d_in[7];
    const float* vstore = (const float*)d_in[8];
    const int*   kvlut  = (const int*)d_in[9];
    const int*   ctxptr = (const int*)d_in[10];
    const int*   prefix = (n_in >= 12) ? (const int*)d_in[11] : nullptr;
    float* out = (float*)d_out;

    __half *qkv, *xh, *wf, *qf, *kf, *vf;
    cudaGetSymbolAddress((void**)&qkv, g_qkv);
    cudaGetSymbolAddress((void**)&xh,  g_xh);
    cudaGetSymbolAddress((void**)&wf,  g_wf);
    cudaGetSymbolAddress((void**)&qf,  g_qf);
    cudaGetSymbolAddress((void**)&kf,  g_kf);
    cudaGetSymbolAddress((void**)&vf,  g_vf);

    cudaFuncSetAttribute(attn_mma, cudaFuncAttributeMaxDynamicSharedMemorySize, ATT_SMEM2);

    // all fp32->fp16 preprocessing in one launch
    prep_all<<<65536, 256>>>(hidden, Wq, Wk, Wv, Wo, kstore, vstore, xh, wf, kf, vf);

    // fused QKV projection (fp16 output)
    gemm_f16_1p<__half><<<dim3(QKVN / 128, MROWS / 128), 256>>>(
        xh, wf, qkv, MROWS, QKVN, HID);

    // RoPE + round + scatter
    rope_scatter_h<<<MROWS, 256>>>(qkv, cosp, sinp, ctxptr, qf, kf, vf);

    // attention (q-tile 64, 4 CTAs/SM target; writes fp16 output into xh)
    attn_mma<<<dim3(QL / 64, NH, BSZ), 128, ATT_SMEM2>>>(
        qf, kf, vf, kvlut, prefix, xh);

    // O projection (fp32 output to d_out)
    gemm_f16_1p<float><<<dim3(HID / 128, MROWS / 128), 256>>>(
        xh, wf + WOFF_O, out, MROWS, HID, HID);
}

// round 15
// speedup vs baseline: 1.2514x; 1.0376x over previous
#include <cuda_runtime.h>
#include <cuda_fp16.h>
#include <cstdint>

// ---------------- problem dims ----------------
#define BSZ   2
#define QL    1024
#define HID   4096
#define NH    32
#define NKV   8
#define HD    128
#define NBLK  512
#define BLKSZ 16
#define SEQ   4096
#define MROWS (BSZ*QL)                 // 2048
#define QKVN  (NH*HD + 2*NKV*HD)       // 6144
#define WROWS (QKVN + HID)             // 10240
#define WOFF_O ((size_t)QKVN * HID)

// q pre-scale: (1/sqrt(128)) * log2(e)  -> softmax in exp2 domain
#define ASCALE ((float)(0.08838834764831845 * 1.4426950408889634))

// ---------------- device scratch ----------------
__device__ __half g_qkv[(size_t)MROWS * QKVN];   // fused QKV projection output (fp16)
__device__ __half g_xh [(size_t)MROWS * HID];    // activations fp16 (reused for attn out)
__device__ __half g_wf [(size_t)WROWS * HID];    // all weights fp16
__device__ __half g_qf [(size_t)BSZ * NH * QL * HD];   // Q fp16 (pre-scaled)
__device__ __half g_kf [(size_t)NBLK * NKV * BLKSZ * HD];  // K cache fp16
__device__ __half g_vf [(size_t)NBLK * NKV * BLKSZ * HD];  // V cache fp16

// ---------------- helpers ----------------
__device__ __forceinline__ uint32_t smem_u32(const void* p) {
    uint32_t a;
    asm("{ .reg .u64 t; cvta.to.shared.u64 t, %1; cvt.u32.u64 %0, t; }" : "=r"(a) : "l"(p));
    return a;
}
__device__ __forceinline__ void ldsm4(uint32_t* r, uint32_t addr) {
    asm volatile("ldmatrix.sync.aligned.m8n8.x4.shared.b16 {%0,%1,%2,%3}, [%4];"
                 : "=r"(r[0]), "=r"(r[1]), "=r"(r[2]), "=r"(r[3]) : "r"(addr));
}
__device__ __forceinline__ void ldsm4t(uint32_t* r, uint32_t addr) {
    asm volatile("ldmatrix.sync.aligned.m8n8.x4.trans.shared.b16 {%0,%1,%2,%3}, [%4];"
                 : "=r"(r[0]), "=r"(r[1]), "=r"(r[2]), "=r"(r[3]) : "r"(addr));
}
__device__ __forceinline__ void mma_f16(float* c, const uint32_t* a, uint32_t b0, uint32_t b1) {
    asm volatile("mma.sync.aligned.m16n8k16.row.col.f32.f16.f16.f32 "
                 "{%0,%1,%2,%3}, {%4,%5,%6,%7}, {%8,%9}, {%0,%1,%2,%3};"
                 : "+f"(c[0]), "+f"(c[1]), "+f"(c[2]), "+f"(c[3])
                 : "r"(a[0]), "r"(a[1]), "r"(a[2]), "r"(a[3]), "r"(b0), "r"(b1));
}
__device__ __forceinline__ float ex2f(float x) {
    float y; asm("ex2.approx.ftz.f32 %0, %1;" : "=f"(y) : "f"(x)); return y;
}
__device__ __forceinline__ uint32_t packh2(float a, float b) {
    __half2 t = __floats2half2_rn(a, b);
    return *(uint32_t*)&t;
}
__device__ __forceinline__ void cpasync16(uint32_t dst, const void* src) {
    asm volatile("cp.async.cg.shared.global [%0], [%1], 16;" :: "r"(dst), "l"(src));
}
#define CP_COMMIT() asm volatile("cp.async.commit_group;" ::: "memory")
#define CP_WAIT1()  asm volatile("cp.async.wait_group 1;" ::: "memory")
#define CP_WAIT0()  asm volatile("cp.async.wait_group 0;" ::: "memory")

// ---------------- fused preprocessing: 7 fp32->fp16 jobs in one launch ----------------
__global__ __launch_bounds__(256) void prep_all(
    const float* __restrict__ hidden,
    const float* __restrict__ Wq, const float* __restrict__ Wk,
    const float* __restrict__ Wv, const float* __restrict__ Wo,
    const float* __restrict__ ks, const float* __restrict__ vs,
    __half* __restrict__ xh, __half* __restrict__ wf,
    __half* __restrict__ kf, __half* __restrict__ vf)
{
    int i = blockIdx.x * 256 + threadIdx.x;
    const float* src; __half* dst; int local;
    if      (i <  2097152) { src = hidden; dst = xh;                       local = i; }
    else if (i <  6291456) { src = Wq;     dst = wf;                       local = i - 2097152; }
    else if (i <  7340032) { src = Wk;     dst = wf + (size_t)16777216;    local = i - 6291456; }
    else if (i <  8388608) { src = Wv;     dst = wf + (size_t)20971520;    local = i - 7340032; }
    else if (i < 12582912) { src = Wo;     dst = wf + (size_t)25165824;    local = i - 8388608; }
    else if (i < 14680064) { src = ks;     dst = kf;                       local = i - 12582912; }
    else                   { src = vs;     dst = vf;                       local = i - 14680064; }
    float4 v = ((const float4*)src)[local];
    __half2* yp = (__half2*)(dst + (size_t)local * 4);
    yp[0] = __floats2half2_rn(v.x, v.y);
    yp[1] = __floats2half2_rn(v.z, v.w);
}

// ---------------- pipelined fp16 single-product GEMM (templated output) ----------------
#define TB2 8192                    // one 128x32 fp16 tile
#define BUF1 (2 * TB2)              // A, B

template <typename OutT>
__global__ __launch_bounds__(256) void gemm_f16_1p(
    const __half* __restrict__ Aa, const __half* __restrict__ Bw,
    OutT* __restrict__ C, int M, int N, int K)
{
    __shared__ __half smem[2][2][128 * 32];   // 32KB

    const int tid  = threadIdx.x;
    const int warp = tid >> 5, lane = tid & 31;
    const int wm = warp & 3, wn = warp >> 2;
    const int bm = blockIdx.y * 128, bn = blockIdx.x * 128;
    const uint32_t sb = smem_u32(smem);

    float acc[2][8][4];
#pragma unroll
    for (int i = 0; i < 2; i++)
#pragma unroll
        for (int j = 0; j < 8; j++)
#pragma unroll
            for (int e = 0; e < 4; e++) acc[i][j][e] = 0.f;

    const __half* g0 = Aa + (size_t)bm * K;
    const __half* g1 = Bw + (size_t)bn * K;

    int rowA = tid >> 2, kcA = tid & 3;
    int rowB = (tid + 256) >> 2, kcB = (tid + 256) & 3;
    uint32_t soffA = (uint32_t)(rowA * 32 + (((kcA + (rowA >> 1)) & 3) * 8)) * 2;
    uint32_t soffB = (uint32_t)(rowB * 32 + (((kcB + (rowB >> 1)) & 3) * 8)) * 2;

    const int nch = K / 32;

#define ISSUE_LOAD(buf, k0)                                                    \
    do {                                                                       \
        size_t gA = (size_t)rowA * K + (k0) + kcA * 8;                         \
        size_t gB = (size_t)rowB * K + (k0) + kcB * 8;                         \
        uint32_t base = sb + (buf) * BUF1;                                     \
        cpasync16(base + 0 * TB2 + soffA, g0 + gA);                            \
        cpasync16(base + 1 * TB2 + soffA, g1 + gA);                            \
        cpasync16(base + 0 * TB2 + soffB, g0 + gB);                            \
        cpasync16(base + 1 * TB2 + soffB, g1 + gB);                            \
        CP_COMMIT();                                                           \
    } while (0)

    ISSUE_LOAD(0, 0);

    for (int ch = 0; ch < nch; ch++) {
        const int buf = ch & 1;
        if (ch + 1 < nch) {
            ISSUE_LOAD(buf ^ 1, (ch + 1) * 32);
            CP_WAIT1();
        } else {
            CP_WAIT0();
        }
        __syncthreads();

        const uint32_t aBs = sb + buf * BUF1;
        const uint32_t bBs = aBs + TB2;

#pragma unroll
        for (int ks = 0; ks < 2; ks++) {
            uint32_t ah[2][4];
            {
                int r  = wm * 32 + (lane & 15);
                int cd = ks * 2 + (lane >> 4);
#pragma unroll
                for (int mt = 0; mt < 2; mt++) {
                    int row  = r + mt * 16;
                    int phys = (cd + (row >> 1)) & 3;
                    uint32_t off = (uint32_t)(row * 32 + phys * 8) * 2;
                    ldsm4(ah[mt], aBs + off);
                }
            }
#pragma unroll
            for (int nt4 = 0; nt4 < 4; nt4++) {
                int n    = wn * 64 + nt4 * 16 + (lane & 7) + ((lane >> 4) << 3);
                int cd   = ks * 2 + ((lane >> 3) & 1);
                int phys = (cd + (n >> 1)) & 3;
                uint32_t off = (uint32_t)(n * 32 + phys * 8) * 2;
                uint32_t bw[4];
                ldsm4(bw, bBs + off);
#pragma unroll
                for (int mt = 0; mt < 2; mt++) {
#pragma unroll
                    for (int p = 0; p < 2; p++) {
                        mma_f16(acc[mt][nt4 * 2 + p], ah[mt], bw[2 * p], bw[2 * p + 1]);
                    }
                }
            }
        }
        __syncthreads();
    }
#undef ISSUE_LOAD

#pragma unroll
    for (int mt = 0; mt < 2; mt++) {
#pragma unroll
        for (int nt = 0; nt < 8; nt++) {
            int row = bm + wm * 32 + mt * 16 + (lane >> 2);
            int col = bn + wn * 64 + nt * 8 + (lane & 3) * 2;
            float* cc = acc[mt][nt];
            if constexpr (sizeof(OutT) == 2) {
                *(uint32_t*)&C[(size_t)row * N + col]       = packh2(cc[0], cc[1]);
                *(uint32_t*)&C[(size_t)(row + 8) * N + col] = packh2(cc[2], cc[3]);
            } else {
                *(float2*)&C[(size_t)row * N + col]       = make_float2(cc[0], cc[1]);
                *(float2*)&C[(size_t)(row + 8) * N + col] = make_float2(cc[2], cc[3]);
            }
        }
    }
}

// ---------------- RoPE + fp16 round + cache scatter (fp16 qkv input) ----------------
__global__ __launch_bounds__(256) void rope_scatter_h(
    const __half* __restrict__ QKV,
    const float* __restrict__ cosp, const float* __restrict__ sinp,
    const int* __restrict__ ctx_ptrs,
    __half* __restrict__ qf,
    __half* __restrict__ kf, __half* __restrict__ vf)
{
    const int row = blockIdx.x;          // 0..2047
    const int b = row >> 10, t = row & 1023;
    const int tid = threadIdx.x;
    const float* crow = cosp + (size_t)t * HD;
    const float* srow = sinp + (size_t)t * HD;
    const __half* Qr = QKV + (size_t)row * QKVN;
    const __half* Kr = Qr + NH * HD;
    const __half* Vr = Kr + NKV * HD;

    for (int idx = tid; idx < NH * 64; idx += 256) {
        int h = idx >> 6, d = idx & 63;
        float x0 = __half2float(Qr[h * HD + d]);
        float x1 = __half2float(Qr[h * HD + d + 64]);
        float o0 = (x0 * crow[d]      - x1 * srow[d])      * ASCALE;
        float o1 = (x1 * crow[d + 64] + x0 * srow[d + 64]) * ASCALE;
        size_t base = ((size_t)(b * NH + h) * QL + t) * HD;
        qf[base + d]      = __float2half_rn(o0);
        qf[base + d + 64] = __float2half_rn(o1);
    }

    const int blk  = ctx_ptrs[b * (QL / BLKSZ) + (t >> 4)];
    const int rrow = t & 15;

    for (int idx = tid; idx < NKV * 64; idx += 256) {
        int h = idx >> 6, d = idx & 63;
        float x0 = __half2float(Kr[h * HD + d]);
        float x1 = __half2float(Kr[h * HD + d + 64]);
        float o0 = x0 * crow[d]      - x1 * srow[d];
        float o1 = x1 * crow[d + 64] + x0 * srow[d + 64];
        size_t base = (((size_t)blk * NKV + h) * BLKSZ + rrow) * HD;
        kf[base + d]      = __float2half_rn(o0);
        kf[base + d + 64] = __float2half_rn(o1);
    }

    for (int idx = tid; idx < NKV * HD; idx += 256) {
        int h = idx >> 7, d = idx & 127;
        vf[(((size_t)blk * NKV + h) * BLKSZ + rrow) * HD + d] = Vr[h * HD + d];
    }
}

// ---------------- flash attention: 2 heads/CTA, pipelined K/V fills ----------------
// 256 threads (8 warps): warps 0-3 -> head hp*2, warps 4-7 -> head hp*2+1.
// smem: Q[2][64][128] + K[64][128] + V[64][128] = 64KB.
// Pipeline: V(s) fill overlaps QK(s); K(s+1) fill overlaps PV(s).
#define ATT_SMEM3 (4 * 64 * 128 * 2)

__global__ __launch_bounds__(256, 2) void attn_mma(
    const __half* __restrict__ gqf,
    const __half* __restrict__ gkf, const __half* __restrict__ gvf,
    const int* __restrict__ kvlut, const int* __restrict__ prefix_ptr,
    __half* __restrict__ oh)
{
    extern __shared__ __align__(16) char dynsm[];
    __half* sQ = (__half*)dynsm;          // 2 x 64 x 128
    __half* sK = sQ + 2 * 64 * 128;       // 64 x 128
    __half* sV = sK + 64 * 128;           // 64 x 128
    const uint32_t bQ = smem_u32(sQ), bK = smem_u32(sK), bV = smem_u32(sV);

    const int qtile = blockIdx.x, hp = blockIdx.y, b = blockIdx.z;
    const int kvh = hp >> 1;
    const int prefix = prefix_ptr ? *prefix_ptr : 3072;
    const int tid = threadIdx.x;
    const int warp = tid >> 5, lane = tid & 31;
    const int hw = warp >> 2;             // head within pair
    const int h = hp * 2 + hw;
    const int qr = (warp & 3) * 16;
    const int q0 = qtile * 64;
    const int* lut = kvlut + b * (SEQ / BLKSZ);
    const uint32_t bQme = bQ + (uint32_t)hw * (64 * 128 * 2);

    const int plim = prefix + q0;
    const int kv_end = plim + 64;
    const int qa0 = plim + qr + (lane >> 2);
    const int qa1 = qa0 + 8;

    // prologue: fill both Q tiles + K(0)
    for (int i = tid; i < 2 * 64 * 16; i += 256) {
        int t = i >> 10;
        int row = (i >> 4) & 63, c = i & 15;
        int phys = (c ^ (row & 7)) << 3;
        const __half* src = gqf + ((size_t)(b * NH + hp * 2 + t) * QL + q0) * HD;
        cpasync16(bQ + (uint32_t)(t * 64 * 128 + row * 128 + phys) * 2,
                  src + (size_t)row * HD + c * 8);
    }
    CP_COMMIT();
    for (int i = tid; i < 64 * 16; i += 256) {
        int row = i >> 4, c = i & 15;
        int blk = lut[row >> 4];
        size_t base = (((size_t)blk * NKV + kvh) * BLKSZ + (row & 15)) * HD + c * 8;
        int phys = (c ^ (row & 7)) << 3;
        cpasync16(bK + (uint32_t)(row * 128 + phys) * 2, gkf + base);
    }
    CP_COMMIT();

    float O[16][4];
#pragma unroll
    for (int i = 0; i < 16; i++)
#pragma unroll
        for (int e = 0; e < 4; e++) O[i][e] = 0.f;
    float m0 = -1e30f, m1 = -1e30f, l0 = 0.f, l1 = 0.f;

    for (int s0 = 0; s0 < kv_end; s0 += 64) {
        CP_WAIT0();            // K(s) (and Q first iter) ready; V buffer free (all prior PV done)
        __syncthreads();

        // issue V(s) fill — overlaps QK compute
        for (int i = tid; i < 64 * 16; i += 256) {
            int row = i >> 4, c = i & 15;
            int s = s0 + row;
            int blk = lut[s >> 4];
            size_t base = (((size_t)blk * NKV + kvh) * BLKSZ + (s & 15)) * HD + c * 8;
            int phys = (c ^ (row & 7)) << 3;
            cpasync16(bV + (uint32_t)(row * 128 + phys) * 2, gvf + base);
        }
        CP_COMMIT();

        // ---- S = Q K^T ----
        float S[8][4];
#pragma unroll
        for (int i = 0; i < 8; i++)
#pragma unroll
            for (int e = 0; e < 4; e++) S[i][e] = 0.f;

#pragma unroll
        for (int ks = 0; ks < 8; ks++) {
            uint32_t aq[4];
            {
                int arow = qr + (lane & 15);
                int ac = ks * 2 + (lane >> 4);
                uint32_t aoff = (uint32_t)(arow * 128 + ((ac ^ (arow & 7)) << 3)) * 2;
                ldsm4(aq, bQme + aoff);
            }
            int brow_b = (lane & 7) + ((lane >> 4) << 3);
            int bc = ks * 2 + ((lane >> 3) & 1);
#pragma unroll
            for (int ng = 0; ng < 4; ng++) {
                int brow = ng * 16 + brow_b;
                uint32_t boff = (uint32_t)(brow * 128 + ((bc ^ (brow & 7)) << 3)) * 2;
                uint32_t kw[4];
                ldsm4(kw, bK + boff);
                mma_f16(S[2 * ng],     aq, kw[0], kw[1]);
                mma_f16(S[2 * ng + 1], aq, kw[2], kw[3]);
            }
        }

        if (s0 + 63 > plim) {
#pragma unroll
            for (int nt = 0; nt < 8; nt++) {
                int colb = s0 + nt * 8 + ((lane & 3) << 1);
                if (colb     > qa0) S[nt][0] = -1e30f;
                if (colb + 1 > qa0) S[nt][1] = -1e30f;
                if (colb     > qa1) S[nt][2] = -1e30f;
                if (colb + 1 > qa1) S[nt][3] = -1e30f;
            }
        }

        // ---- online softmax (base-2) ----
        float mx0 = -1e30f, mx1 = -1e30f;
#pragma unroll
        for (int nt = 0; nt < 8; nt++) {
            mx0 = fmaxf(mx0, fmaxf(S[nt][0], S[nt][1]));
            mx1 = fmaxf(mx1, fmaxf(S[nt][2], S[nt][3]));
        }
        mx0 = fmaxf(mx0, __shfl_xor_sync(0xffffffffu, mx0, 1));
        mx0 = fmaxf(mx0, __shfl_xor_sync(0xffffffffu, mx0, 2));
        mx1 = fmaxf(mx1, __shfl_xor_sync(0xffffffffu, mx1, 1));
        mx1 = fmaxf(mx1, __shfl_xor_sync(0xffffffffu, mx1, 2));
        float mn0 = fmaxf(m0, mx0), mn1 = fmaxf(m1, mx1);
        float f0 = ex2f(m0 - mn0), f1 = ex2f(m1 - mn1);
        m0 = mn0; m1 = mn1;

        float rs0 = 0.f, rs1 = 0.f;
#pragma unroll
        for (int nt = 0; nt < 8; nt++) {
            S[nt][0] = ex2f(S[nt][0] - mn0); rs0 += S[nt][0];
            S[nt][1] = ex2f(S[nt][1] - mn0); rs0 += S[nt][1];
            S[nt][2] = ex2f(S[nt][2] - mn1); rs1 += S[nt][2];
            S[nt][3] = ex2f(S[nt][3] - mn1); rs1 += S[nt][3];
        }
        rs0 += __shfl_xor_sync(0xffffffffu, rs0, 1);
        rs0 += __shfl_xor_sync(0xffffffffu, rs0, 2);
        rs1 += __shfl_xor_sync(0xffffffffu, rs1, 1);
        rs1 += __shfl_xor_sync(0xffffffffu, rs1, 2);
        l0 = l0 * f0 + rs0;
        l1 = l1 * f1 + rs1;

#pragma unroll
        for (int nt = 0; nt < 16; nt++) {
            O[nt][0] *= f0; O[nt][1] *= f0; O[nt][2] *= f1; O[nt][3] *= f1;
        }

        // ---- pack P ----
        uint32_t PH[4][4];
#pragma unroll
        for (int kt = 0; kt < 4; kt++) {
            int e = 2 * kt, o = 2 * kt + 1;
            PH[kt][0] = packh2(S[e][0], S[e][1]);
            PH[kt][1] = packh2(S[e][2], S[e][3]);
            PH[kt][2] = packh2(S[o][0], S[o][1]);
            PH[kt][3] = packh2(S[o][2], S[o][3]);
        }

        CP_WAIT0();            // V(s) ready; K buffer free (all warps past QK)
        __syncthreads();

        // issue K(s+1) fill — overlaps PV compute
        if (s0 + 64 < kv_end) {
            int sn = s0 + 64;
            for (int i = tid; i < 64 * 16; i += 256) {
                int row = i >> 4, c = i & 15;
                int s = sn + row;
                int blk = lut[s >> 4];
                size_t base = (((size_t)blk * NKV + kvh) * BLKSZ + (s & 15)) * HD + c * 8;
                int phys = (c ^ (row & 7)) << 3;
                cpasync16(bK + (uint32_t)(row * 128 + phys) * 2, gkf + base);
            }
            CP_COMMIT();
        } else {
            CP_COMMIT();       // keep group count consistent for final CP_WAIT0 (empty group)
        }

        // ---- O += P V ----
#pragma unroll
        for (int kt = 0; kt < 4; kt++) {
            int vrow = kt * 16 + (((lane >> 3) & 1) << 3) + (lane & 7);
            int vc0 = lane >> 4;
#pragma unroll
            for (int vg = 0; vg < 8; vg++) {
                int c = vg * 2 + vc0;
                uint32_t off = (uint32_t)(vrow * 128 + ((c ^ (vrow & 7)) << 3)) * 2;
                uint32_t vw[4];
                ldsm4t(vw, bV + off);
                mma_f16(O[2 * vg],     PH[kt], vw[0], vw[1]);
                mma_f16(O[2 * vg + 1], PH[kt], vw[2], vw[3]);
            }
        }
    }

    // epilogue: normalize, round to fp16, write [b,t,h*128+d]
    float inv0 = 1.f / l0, inv1 = 1.f / l1;
    int r0 = q0 + qr + (lane >> 2);
    int r1 = r0 + 8;
#pragma unroll
    for (int nt = 0; nt < 16; nt++) {
        int d = h * HD + nt * 8 + ((lane & 3) << 1);
        *(uint32_t*)(oh + (size_t)(b * QL + r0) * HID + d) =
            packh2(O[nt][0] * inv0, O[nt][1] * inv0);
        *(uint32_t*)(oh + (size_t)(b * QL + r1) * HID + d) =
            packh2(O[nt][2] * inv1, O[nt][3] * inv1);
    }
}

// ---------------- launcher ----------------
extern "C" void kernel_launch(void* const* d_in, const int* in_sizes, int n_in,
                              void* d_out, int out_size)
{
    const float* hidden = (const float*)d_in[0];
    const float* Wq     = (const float*)d_in[1];
    const float* Wk     = (const float*)d_in[2];
    const float* Wv     = (const float*)d_in[3];
    const float* Wo     = (const float*)d_in[4];
    const float* cosp   = (const float*)d_in[5];
    const float* sinp   = (const float*)d_in[6];
    const float* kstore = (const float*)d_in[7];
    const float* vstore = (const float*)d_in[8];
    const int*   kvlut  = (const int*)d_in[9];
    const int*   ctxptr = (const int*)d_in[10];
    const int*   prefix = (n_in >= 12) ? (const int*)d_in[11] : nullptr;
    float* out = (float*)d_out;

    __half *qkv, *xh, *wf, *qf, *kf, *vf;
    cudaGetSymbolAddress((void**)&qkv, g_qkv);
    cudaGetSymbolAddress((void**)&xh,  g_xh);
    cudaGetSymbolAddress((void**)&wf,  g_wf);
    cudaGetSymbolAddress((void**)&qf,  g_qf);
    cudaGetSymbolAddress((void**)&kf,  g_kf);
    cudaGetSymbolAddress((void**)&vf,  g_vf);

    cudaFuncSetAttribute(attn_mma, cudaFuncAttributeMaxDynamicSharedMemorySize, ATT_SMEM3);

    // all fp32->fp16 preprocessing in one launch
    prep_all<<<65536, 256>>>(hidden, Wq, Wk, Wv, Wo, kstore, vstore, xh, wf, kf, vf);

    // fused QKV projection (fp16 output)
    gemm_f16_1p<__half><<<dim3(QKVN / 128, MROWS / 128), 256>>>(
        xh, wf, qkv, MROWS, QKVN, HID);

    // RoPE + round + scatter
    rope_scatter_h<<<MROWS, 256>>>(qkv, cosp, sinp, ctxptr, qf, kf, vf);

    // attention: 2 heads/CTA, pipelined fills
    attn_mma<<<dim3(QL / 64, NH / 2, BSZ), 256, ATT_SMEM3>>>(
        qf, kf, vf, kvlut, prefix, xh);

    // O projection (fp32 output to d_out)
    gemm_f16_1p<float><<<dim3(HID / 128, MROWS / 128), 256>>>(
        xh, wf + WOFF_O, out, MROWS, HID, HID);
}

// round 16
// speedup vs baseline: 1.3153x; 1.0510x over previous
#include <cuda_runtime.h>
#include <cuda_fp16.h>
#include <cstdint>

// ---------------- problem dims ----------------
#define BSZ   2
#define QL    1024
#define HID   4096
#define NH    32
#define NKV   8
#define HD    128
#define NBLK  512
#define BLKSZ 16
#define SEQ   4096
#define MROWS (BSZ*QL)                 // 2048
#define QKVN  (NH*HD + 2*NKV*HD)       // 6144
#define WROWS (QKVN + HID)             // 10240
#define WOFF_O ((size_t)QKVN * HID)

// q pre-scale: (1/sqrt(128)) * log2(e)  -> softmax in exp2 domain
#define ASCALE ((float)(0.08838834764831845 * 1.4426950408889634))

// ---------------- device scratch ----------------
__device__ __half g_qkv[(size_t)MROWS * QKVN];   // fused QKV projection output (fp16)
__device__ __half g_xh [(size_t)MROWS * HID];    // activations fp16 (reused for attn out)
__device__ __half g_wf [(size_t)WROWS * HID];    // all weights fp16
__device__ __half g_qf [(size_t)BSZ * NH * QL * HD];   // Q fp16 (pre-scaled)
__device__ __half g_kf [(size_t)NBLK * NKV * BLKSZ * HD];  // K cache fp16
__device__ __half g_vf [(size_t)NBLK * NKV * BLKSZ * HD];  // V cache fp16

// ---------------- helpers ----------------
__device__ __forceinline__ uint32_t smem_u32(const void* p) {
    uint32_t a;
    asm("{ .reg .u64 t; cvta.to.shared.u64 t, %1; cvt.u32.u64 %0, t; }" : "=r"(a) : "l"(p));
    return a;
}
__device__ __forceinline__ void ldsm4(uint32_t* r, uint32_t addr) {
    asm volatile("ldmatrix.sync.aligned.m8n8.x4.shared.b16 {%0,%1,%2,%3}, [%4];"
                 : "=r"(r[0]), "=r"(r[1]), "=r"(r[2]), "=r"(r[3]) : "r"(addr));
}
__device__ __forceinline__ void ldsm4t(uint32_t* r, uint32_t addr) {
    asm volatile("ldmatrix.sync.aligned.m8n8.x4.trans.shared.b16 {%0,%1,%2,%3}, [%4];"
                 : "=r"(r[0]), "=r"(r[1]), "=r"(r[2]), "=r"(r[3]) : "r"(addr));
}
__device__ __forceinline__ void mma_f16(float* c, const uint32_t* a, uint32_t b0, uint32_t b1) {
    asm volatile("mma.sync.aligned.m16n8k16.row.col.f32.f16.f16.f32 "
                 "{%0,%1,%2,%3}, {%4,%5,%6,%7}, {%8,%9}, {%0,%1,%2,%3};"
                 : "+f"(c[0]), "+f"(c[1]), "+f"(c[2]), "+f"(c[3])
                 : "r"(a[0]), "r"(a[1]), "r"(a[2]), "r"(a[3]), "r"(b0), "r"(b1));
}
__device__ __forceinline__ float ex2f(float x) {
    float y; asm("ex2.approx.ftz.f32 %0, %1;" : "=f"(y) : "f"(x)); return y;
}
__device__ __forceinline__ uint32_t packh2(float a, float b) {
    __half2 t = __floats2half2_rn(a, b);
    return *(uint32_t*)&t;
}
__device__ __forceinline__ void cpasync16(uint32_t dst, const void* src) {
    asm volatile("cp.async.cg.shared.global [%0], [%1], 16;" :: "r"(dst), "l"(src));
}
#define CP_COMMIT() asm volatile("cp.async.commit_group;" ::: "memory")
#define CP_WAIT1()  asm volatile("cp.async.wait_group 1;" ::: "memory")
#define CP_WAIT0()  asm volatile("cp.async.wait_group 0;" ::: "memory")

// ---------------- fused preprocessing: 7 fp32->fp16 jobs, 2 float4/thread ----------------
__global__ __launch_bounds__(256) void prep_all(
    const float* __restrict__ hidden,
    const float* __restrict__ Wq, const float* __restrict__ Wk,
    const float* __restrict__ Wv, const float* __restrict__ Wo,
    const float* __restrict__ ks, const float* __restrict__ vs,
    __half* __restrict__ xh, __half* __restrict__ wf,
    __half* __restrict__ kf, __half* __restrict__ vf)
{
    int j = blockIdx.x * 256 + threadIdx.x;
    int i = j * 2;                       // first float4 index; pair stays in one segment
    const float* src; __half* dst; int local;
    if      (i <  2097152) { src = hidden; dst = xh;                       local = i; }
    else if (i <  6291456) { src = Wq;     dst = wf;                       local = i - 2097152; }
    else if (i <  7340032) { src = Wk;     dst = wf + (size_t)16777216;    local = i - 6291456; }
    else if (i <  8388608) { src = Wv;     dst = wf + (size_t)20971520;    local = i - 7340032; }
    else if (i < 12582912) { src = Wo;     dst = wf + (size_t)25165824;    local = i - 8388608; }
    else if (i < 14680064) { src = ks;     dst = kf;                       local = i - 12582912; }
    else                   { src = vs;     dst = vf;                       local = i - 14680064; }
    float4 v0 = ((const float4*)src)[local];
    float4 v1 = ((const float4*)src)[local + 1];
    __half2* yp = (__half2*)(dst + (size_t)local * 4);
    yp[0] = __floats2half2_rn(v0.x, v0.y);
    yp[1] = __floats2half2_rn(v0.z, v0.w);
    yp[2] = __floats2half2_rn(v1.x, v1.y);
    yp[3] = __floats2half2_rn(v1.z, v1.w);
}

// ---------------- pipelined fp16 single-product GEMM (templated output) ----------------
#define TB2 8192                    // one 128x32 fp16 tile
#define BUF1 (2 * TB2)              // A, B

template <typename OutT>
__global__ __launch_bounds__(256) void gemm_f16_1p(
    const __half* __restrict__ Aa, const __half* __restrict__ Bw,
    OutT* __restrict__ C, int M, int N, int K)
{
    __shared__ __half smem[2][2][128 * 32];   // 32KB

    const int tid  = threadIdx.x;
    const int warp = tid >> 5, lane = tid & 31;
    const int wm = warp & 3, wn = warp >> 2;
    const int bm = blockIdx.y * 128, bn = blockIdx.x * 128;
    const uint32_t sb = smem_u32(smem);

    float acc[2][8][4];
#pragma unroll
    for (int i = 0; i < 2; i++)
#pragma unroll
        for (int j = 0; j < 8; j++)
#pragma unroll
            for (int e = 0; e < 4; e++) acc[i][j][e] = 0.f;

    const __half* g0 = Aa + (size_t)bm * K;
    const __half* g1 = Bw + (size_t)bn * K;

    int rowA = tid >> 2, kcA = tid & 3;
    int rowB = (tid + 256) >> 2, kcB = (tid + 256) & 3;
    uint32_t soffA = (uint32_t)(rowA * 32 + (((kcA + (rowA >> 1)) & 3) * 8)) * 2;
    uint32_t soffB = (uint32_t)(rowB * 32 + (((kcB + (rowB >> 1)) & 3) * 8)) * 2;

    const int nch = K / 32;

#define ISSUE_LOAD(buf, k0)                                                    \
    do {                                                                       \
        size_t gA = (size_t)rowA * K + (k0) + kcA * 8;                         \
        size_t gB = (size_t)rowB * K + (k0) + kcB * 8;                         \
        uint32_t base = sb + (buf) * BUF1;                                     \
        cpasync16(base + 0 * TB2 + soffA, g0 + gA);                            \
        cpasync16(base + 1 * TB2 + soffA, g1 + gA);                            \
        cpasync16(base + 0 * TB2 + soffB, g0 + gB);                            \
        cpasync16(base + 1 * TB2 + soffB, g1 + gB);                            \
        CP_COMMIT();                                                           \
    } while (0)

    ISSUE_LOAD(0, 0);

    for (int ch = 0; ch < nch; ch++) {
        const int buf = ch & 1;
        if (ch + 1 < nch) {
            ISSUE_LOAD(buf ^ 1, (ch + 1) * 32);
            CP_WAIT1();
        } else {
            CP_WAIT0();
        }
        __syncthreads();

        const uint32_t aBs = sb + buf * BUF1;
        const uint32_t bBs = aBs + TB2;

#pragma unroll
        for (int ks = 0; ks < 2; ks++) {
            uint32_t ah[2][4];
            {
                int r  = wm * 32 + (lane & 15);
                int cd = ks * 2 + (lane >> 4);
#pragma unroll
                for (int mt = 0; mt < 2; mt++) {
                    int row  = r + mt * 16;
                    int phys = (cd + (row >> 1)) & 3;
                    uint32_t off = (uint32_t)(row * 32 + phys * 8) * 2;
                    ldsm4(ah[mt], aBs + off);
                }
            }
#pragma unroll
            for (int nt4 = 0; nt4 < 4; nt4++) {
                int n    = wn * 64 + nt4 * 16 + (lane & 7) + ((lane >> 4) << 3);
                int cd   = ks * 2 + ((lane >> 3) & 1);
                int phys = (cd + (n >> 1)) & 3;
                uint32_t off = (uint32_t)(n * 32 + phys * 8) * 2;
                uint32_t bw[4];
                ldsm4(bw, bBs + off);
#pragma unroll
                for (int mt = 0; mt < 2; mt++) {
#pragma unroll
                    for (int p = 0; p < 2; p++) {
                        mma_f16(acc[mt][nt4 * 2 + p], ah[mt], bw[2 * p], bw[2 * p + 1]);
                    }
                }
            }
        }
        __syncthreads();
    }
#undef ISSUE_LOAD

#pragma unroll
    for (int mt = 0; mt < 2; mt++) {
#pragma unroll
        for (int nt = 0; nt < 8; nt++) {
            int row = bm + wm * 32 + mt * 16 + (lane >> 2);
            int col = bn + wn * 64 + nt * 8 + (lane & 3) * 2;
            float* cc = acc[mt][nt];
            if constexpr (sizeof(OutT) == 2) {
                *(uint32_t*)&C[(size_t)row * N + col]       = packh2(cc[0], cc[1]);
                *(uint32_t*)&C[(size_t)(row + 8) * N + col] = packh2(cc[2], cc[3]);
            } else {
                *(float2*)&C[(size_t)row * N + col]       = make_float2(cc[0], cc[1]);
                *(float2*)&C[(size_t)(row + 8) * N + col] = make_float2(cc[2], cc[3]);
            }
        }
    }
}

// ---------------- RoPE + fp16 round + cache scatter (fp16 qkv input) ----------------
__global__ __launch_bounds__(256) void rope_scatter_h(
    const __half* __restrict__ QKV,
    const float* __restrict__ cosp, const float* __restrict__ sinp,
    const int* __restrict__ ctx_ptrs,
    __half* __restrict__ qf,
    __half* __restrict__ kf, __half* __restrict__ vf)
{
    const int row = blockIdx.x;          // 0..2047
    const int b = row >> 10, t = row & 1023;
    const int tid = threadIdx.x;
    const float* crow = cosp + (size_t)t * HD;
    const float* srow = sinp + (size_t)t * HD;
    const __half* Qr = QKV + (size_t)row * QKVN;
    const __half* Kr = Qr + NH * HD;
    const __half* Vr = Kr + NKV * HD;

    for (int idx = tid; idx < NH * 64; idx += 256) {
        int h = idx >> 6, d = idx & 63;
        float x0 = __half2float(Qr[h * HD + d]);
        float x1 = __half2float(Qr[h * HD + d + 64]);
        float o0 = (x0 * crow[d]      - x1 * srow[d])      * ASCALE;
        float o1 = (x1 * crow[d + 64] + x0 * srow[d + 64]) * ASCALE;
        size_t base = ((size_t)(b * NH + h) * QL + t) * HD;
        qf[base + d]      = __float2half_rn(o0);
        qf[base + d + 64] = __float2half_rn(o1);
    }

    const int blk  = ctx_ptrs[b * (QL / BLKSZ) + (t >> 4)];
    const int rrow = t & 15;

    for (int idx = tid; idx < NKV * 64; idx += 256) {
        int h = idx >> 6, d = idx & 63;
        float x0 = __half2float(Kr[h * HD + d]);
        float x1 = __half2float(Kr[h * HD + d + 64]);
        float o0 = x0 * crow[d]      - x1 * srow[d];
        float o1 = x1 * crow[d + 64] + x0 * srow[d + 64];
        size_t base = (((size_t)blk * NKV + h) * BLKSZ + rrow) * HD;
        kf[base + d]      = __float2half_rn(o0);
        kf[base + d + 64] = __float2half_rn(o1);
    }

    for (int idx = tid; idx < NKV * HD; idx += 256) {
        int h = idx >> 7, d = idx & 127;
        vf[(((size_t)blk * NKV + h) * BLKSZ + rrow) * HD + d] = Vr[h * HD + d];
    }
}

// ---------------- flash attention: 2 heads/CTA, pipelined fills, hoisted LUT ----------------
// 256 threads (8 warps): warps 0-3 -> head hp*2, warps 4-7 -> head hp*2+1.
// smem: Q[2][64][128] + K[64][128] + V[64][128] = 64KB.
// Pipeline: V(s) fill overlaps QK(s); K(s+1) fill overlaps PV(s).
// LUT hoisted: one int4 load per tile covers all 1024 fill iterations.
#define ATT_SMEM3 (4 * 64 * 128 * 2)

__global__ __launch_bounds__(256, 2) void attn_mma(
    const __half* __restrict__ gqf,
    const __half* __restrict__ gkf, const __half* __restrict__ gvf,
    const int* __restrict__ kvlut, const int* __restrict__ prefix_ptr,
    __half* __restrict__ oh)
{
    extern __shared__ __align__(16) char dynsm[];
    __half* sQ = (__half*)dynsm;          // 2 x 64 x 128
    __half* sK = sQ + 2 * 64 * 128;       // 64 x 128
    __half* sV = sK + 64 * 128;           // 64 x 128
    const uint32_t bQ = smem_u32(sQ), bK = smem_u32(sK), bV = smem_u32(sV);

    const int qtile = blockIdx.x, hp = blockIdx.y, b = blockIdx.z;
    const int kvh = hp >> 1;
    const int prefix = prefix_ptr ? *prefix_ptr : 3072;
    const int tid = threadIdx.x;
    const int warp = tid >> 5, lane = tid & 31;
    const int hw = warp >> 2;             // head within pair
    const int h = hp * 2 + hw;
    const int qr = (warp & 3) * 16;
    const int q0 = qtile * 64;
    const int* lut = kvlut + b * (SEQ / BLKSZ);
    const uint32_t bQme = bQ + (uint32_t)hw * (64 * 128 * 2);

    const int plim = prefix + q0;
    const int kv_end = plim + 64;
    const int qa0 = plim + qr + (lane >> 2);
    const int qa1 = qa0 + 8;

    // per-thread fill geometry (constant across tiles/iterations)
    const int frow = tid >> 4;            // row within 16-block AND row&15; 0..15
    const int fc   = tid & 15;            // 16B chunk
    const int fphys = (fc ^ (frow & 7)) << 3;
    const uint32_t fsoff0 = (uint32_t)(frow * 128 + fphys) * 2;  // iteration it adds it*16*128*2
    const size_t fgoff = (size_t)(kvh * BLKSZ + frow) * HD + fc * 8;

#define FILL_TILE(dstb, gsrc, blks)                                            \
    do {                                                                       \
        const int* _bp = (const int*)&(blks);                                  \
        _Pragma("unroll")                                                      \
        for (int it = 0; it < 4; it++) {                                       \
            cpasync16((dstb) + fsoff0 + (uint32_t)it * (16 * 128 * 2),         \
                      (gsrc) + (size_t)_bp[it] * (NKV * BLKSZ * HD) + fgoff);  \
        }                                                                      \
    } while (0)

    // prologue: fill both Q tiles + K(0)
    for (int i = tid; i < 2 * 64 * 16; i += 256) {
        int t = i >> 10;
        int row = (i >> 4) & 63, c = i & 15;
        int phys = (c ^ (row & 7)) << 3;
        const __half* src = gqf + ((size_t)(b * NH + hp * 2 + t) * QL + q0) * HD;
        cpasync16(bQ + (uint32_t)(t * 64 * 128 + row * 128 + phys) * 2,
                  src + (size_t)row * HD + c * 8);
    }
    CP_COMMIT();
    int4 blks = *(const int4*)(lut + 0);
    FILL_TILE(bK, gkf, blks);
    CP_COMMIT();

    float O[16][4];
#pragma unroll
    for (int i = 0; i < 16; i++)
#pragma unroll
        for (int e = 0; e < 4; e++) O[i][e] = 0.f;
    float m0 = -1e30f, m1 = -1e30f, l0 = 0.f, l1 = 0.f;

    for (int s0 = 0; s0 < kv_end; s0 += 64) {
        CP_WAIT0();            // K(s) (and Q first iter) ready; V buffer free
        __syncthreads();

        // issue V(s) fill — overlaps QK compute (same blks as K(s))
        FILL_TILE(bV, gvf, blks);
        CP_COMMIT();

        // ---- S = Q K^T ----
        float S[8][4];
#pragma unroll
        for (int i = 0; i < 8; i++)
#pragma unroll
            for (int e = 0; e < 4; e++) S[i][e] = 0.f;

#pragma unroll
        for (int ks = 0; ks < 8; ks++) {
            uint32_t aq[4];
            {
                int arow = qr + (lane & 15);
                int ac = ks * 2 + (lane >> 4);
                uint32_t aoff = (uint32_t)(arow * 128 + ((ac ^ (arow & 7)) << 3)) * 2;
                ldsm4(aq, bQme + aoff);
            }
            int brow_b = (lane & 7) + ((lane >> 4) << 3);
            int bc = ks * 2 + ((lane >> 3) & 1);
#pragma unroll
            for (int ng = 0; ng < 4; ng++) {
                int brow = ng * 16 + brow_b;
                uint32_t boff = (uint32_t)(brow * 128 + ((bc ^ (brow & 7)) << 3)) * 2;
                uint32_t kw[4];
                ldsm4(kw, bK + boff);
                mma_f16(S[2 * ng],     aq, kw[0], kw[1]);
                mma_f16(S[2 * ng + 1], aq, kw[2], kw[3]);
            }
        }

        if (s0 + 63 > plim) {
#pragma unroll
            for (int nt = 0; nt < 8; nt++) {
                int colb = s0 + nt * 8 + ((lane & 3) << 1);
                if (colb     > qa0) S[nt][0] = -1e30f;
                if (colb + 1 > qa0) S[nt][1] = -1e30f;
                if (colb     > qa1) S[nt][2] = -1e30f;
                if (colb + 1 > qa1) S[nt][3] = -1e30f;
            }
        }

        // ---- online softmax (base-2) ----
        float mx0 = -1e30f, mx1 = -1e30f;
#pragma unroll
        for (int nt = 0; nt < 8; nt++) {
            mx0 = fmaxf(mx0, fmaxf(S[nt][0], S[nt][1]));
            mx1 = fmaxf(mx1, fmaxf(S[nt][2], S[nt][3]));
        }
        mx0 = fmaxf(mx0, __shfl_xor_sync(0xffffffffu, mx0, 1));
        mx0 = fmaxf(mx0, __shfl_xor_sync(0xffffffffu, mx0, 2));
        mx1 = fmaxf(mx1, __shfl_xor_sync(0xffffffffu, mx1, 1));
        mx1 = fmaxf(mx1, __shfl_xor_sync(0xffffffffu, mx1, 2));
        float mn0 = fmaxf(m0, mx0), mn1 = fmaxf(m1, mx1);
        float f0 = ex2f(m0 - mn0), f1 = ex2f(m1 - mn1);
        m0 = mn0; m1 = mn1;

        float rs0 = 0.f, rs1 = 0.f;
#pragma unroll
        for (int nt = 0; nt < 8; nt++) {
            S[nt][0] = ex2f(S[nt][0] - mn0); rs0 += S[nt][0];
            S[nt][1] = ex2f(S[nt][1] - mn0); rs0 += S[nt][1];
            S[nt][2] = ex2f(S[nt][2] - mn1); rs1 += S[nt][2];
            S[nt][3] = ex2f(S[nt][3] - mn1); rs1 += S[nt][3];
        }
        rs0 += __shfl_xor_sync(0xffffffffu, rs0, 1);
        rs0 += __shfl_xor_sync(0xffffffffu, rs0, 2);
        rs1 += __shfl_xor_sync(0xffffffffu, rs1, 1);
        rs1 += __shfl_xor_sync(0xffffffffu, rs1, 2);
        l0 = l0 * f0 + rs0;
        l1 = l1 * f1 + rs1;

#pragma unroll
        for (int nt = 0; nt < 16; nt++) {
            O[nt][0] *= f0; O[nt][1] *= f0; O[nt][2] *= f1; O[nt][3] *= f1;
        }

        // ---- pack P ----
        uint32_t PH[4][4];
#pragma unroll
        for (int kt = 0; kt < 4; kt++) {
            int e = 2 * kt, o = 2 * kt + 1;
            PH[kt][0] = packh2(S[e][0], S[e][1]);
            PH[kt][1] = packh2(S[e][2], S[e][3]);
            PH[kt][2] = packh2(S[o][0], S[o][1]);
            PH[kt][3] = packh2(S[o][2], S[o][3]);
        }

        CP_WAIT0();            // V(s) ready; K buffer free (all warps past QK)
        __syncthreads();

        // issue K(s+1) fill — overlaps PV compute
        if (s0 + 64 < kv_end) {
            blks = *(const int4*)(lut + ((s0 + 64) >> 4));
            FILL_TILE(bK, gkf, blks);
            CP_COMMIT();
        } else {
            CP_COMMIT();       // keep group count consistent for final CP_WAIT0
        }

        // ---- O += P V ----
#pragma unroll
        for (int kt = 0; kt < 4; kt++) {
            int vrow = kt * 16 + (((lane >> 3) & 1) << 3) + (lane & 7);
            int vc0 = lane >> 4;
#pragma unroll
            for (int vg = 0; vg < 8; vg++) {
                int c = vg * 2 + vc0;
                uint32_t off = (uint32_t)(vrow * 128 + ((c ^ (vrow & 7)) << 3)) * 2;
                uint32_t vw[4];
                ldsm4t(vw, bV + off);
                mma_f16(O[2 * vg],     PH[kt], vw[0], vw[1]);
                mma_f16(O[2 * vg + 1], PH[kt], vw[2], vw[3]);
            }
        }
    }
#undef FILL_TILE

    // epilogue: normalize, round to fp16, write [b,t,h*128+d]
    float inv0 = 1.f / l0, inv1 = 1.f / l1;
    int r0 = q0 + qr + (lane >> 2);
    int r1 = r0 + 8;
#pragma unroll
    for (int nt = 0; nt < 16; nt++) {
        int d = h * HD + nt * 8 + ((lane & 3) << 1);
        *(uint32_t*)(oh + (size_t)(b * QL + r0) * HID + d) =
            packh2(O[nt][0] * inv0, O[nt][1] * inv0);
        *(uint32_t*)(oh + (size_t)(b * QL + r1) * HID + d) =
            packh2(O[nt][2] * inv1, O[nt][3] * inv1);
    }
}

// ---------------- launcher ----------------
extern "C" void kernel_launch(void* const* d_in, const int* in_sizes, int n_in,
                              void* d_out, int out_size)
{
    const float* hidden = (const float*)d_in[0];
    const float* Wq     = (const float*)d_in[1];
    const float* Wk     = (const float*)d_in[2];
    const float* Wv     = (const float*)d_in[3];
    const float* Wo     = (const float*)d_in[4];
    const float* cosp   = (const float*)d_in[5];
    const float* sinp   = (const float*)d_in[6];
    const float* kstore = (const float*)d_in[7];
    const float* vstore = (const float*)d_in[8];
    const int*   kvlut  = (const int*)d_in[9];
    const int*   ctxptr = (const int*)d_in[10];
    const int*   prefix = (n_in >= 12) ? (const int*)d_in[11] : nullptr;
    float* out = (float*)d_out;

    __half *qkv, *xh, *wf, *qf, *kf, *vf;
    cudaGetSymbolAddress((void**)&qkv, g_qkv);
    cudaGetSymbolAddress((void**)&xh,  g_xh);
    cudaGetSymbolAddress((void**)&wf,  g_wf);
    cudaGetSymbolAddress((void**)&qf,  g_qf);
    cudaGetSymbolAddress((void**)&kf,  g_kf);
    cudaGetSymbolAddress((void**)&vf,  g_vf);

    cudaFuncSetAttribute(attn_mma, cudaFuncAttributeMaxDynamicSharedMemorySize, ATT_SMEM3);

    // all fp32->fp16 preprocessing in one launch (2 float4 per thread)
    prep_all<<<32768, 256>>>(hidden, Wq, Wk, Wv, Wo, kstore, vstore, xh, wf, kf, vf);

    // fused QKV projection (fp16 output)
    gemm_f16_1p<__half><<<dim3(QKVN / 128, MROWS / 128), 256>>>(
        xh, wf, qkv, MROWS, QKVN, HID);

    // RoPE + round + scatter
    rope_scatter_h<<<MROWS, 256>>>(qkv, cosp, sinp, ctxptr, qf, kf, vf);

    // attention: 2 heads/CTA, pipelined fills, hoisted LUT
    attn_mma<<<dim3(QL / 64, NH / 2, BSZ), 256, ATT_SMEM3>>>(
        qf, kf, vf, kvlut, prefix, xh);

    // O projection (fp32 output to d_out)
    gemm_f16_1p<float><<<dim3(HID / 128, MROWS / 128), 256>>>(
        xh, wf + WOFF_O, out, MROWS, HID, HID);
}